// round 12
// baseline (speedup 1.0000x reference)
#include <cuda_runtime.h>
#include <cstdint>

#define TPB 256
#define BM 128
#define BN 128
#define BK 32         // 32 int8 elements per k-tile = 8 u32 per row
#define STRIDE 12     // 8 data u32 + 4 pad: fragment LDS bank-conflict-free (verified perm mod 32)
#define QSCALE 31.75f            // 127/4  (4-sigma clip for N(0,1) data)
#define QINV2  (1.0f / (31.75f * 31.75f))

// Scratch (no cudaMalloc allowed): s[b,c] = ||center_c||^2 - 2 * f_b . c_c
__device__ float g_d2[16384 * 1000];
__device__ float g_c2[4096];

// ---------------- reductions ----------------
__device__ __forceinline__ float warpReduceSum(float v) {
    #pragma unroll
    for (int o = 16; o > 0; o >>= 1) v += __shfl_xor_sync(0xffffffffu, v, o);
    return v;
}
__device__ __forceinline__ float warpReduceMin(float v) {
    #pragma unroll
    for (int o = 16; o > 0; o >>= 1) v = fminf(v, __shfl_xor_sync(0xffffffffu, v, o));
    return v;
}
__device__ __forceinline__ float warpReduceMax(float v) {
    #pragma unroll
    for (int o = 16; o > 0; o >>= 1) v = fmaxf(v, __shfl_xor_sync(0xffffffffu, v, o));
    return v;
}
__device__ __forceinline__ float blockReduceSum(float v, float* red) {
    __syncthreads();
    v = warpReduceSum(v);
    int w = threadIdx.x >> 5, l = threadIdx.x & 31;
    if (l == 0) red[w] = v;
    __syncthreads();
    if (w == 0) {
        float x = (l < (int)(blockDim.x >> 5)) ? red[l] : 0.0f;
        x = warpReduceSum(x);
        if (l == 0) red[0] = x;
    }
    __syncthreads();
    return red[0];
}
__device__ __forceinline__ float blockReduceMin(float v, float* red) {
    __syncthreads();
    v = warpReduceMin(v);
    int w = threadIdx.x >> 5, l = threadIdx.x & 31;
    if (l == 0) red[w] = v;
    __syncthreads();
    if (w == 0) {
        float x = (l < (int)(blockDim.x >> 5)) ? red[l] : 3.4e38f;
        x = warpReduceMin(x);
        if (l == 0) red[0] = x;
    }
    __syncthreads();
    return red[0];
}
__device__ __forceinline__ float blockReduceMax(float v, float* red) {
    __syncthreads();
    v = warpReduceMax(v);
    int w = threadIdx.x >> 5, l = threadIdx.x & 31;
    if (l == 0) red[w] = v;
    __syncthreads();
    if (w == 0) {
        float x = (l < (int)(blockDim.x >> 5)) ? red[l] : -3.4e38f;
        x = warpReduceMax(x);
        if (l == 0) red[0] = x;
    }
    __syncthreads();
    return red[0];
}

// ---------------- softmax over classes ----------------
__global__ void __launch_bounds__(TPB) softmax_kernel(
    const float* __restrict__ P, float* __restrict__ out, int C)
{
    __shared__ float red[8];
    int b = blockIdx.x;
    const float* row = P + (size_t)b * C;
    float v[4];
    int cnt = 0;
    float mx = -3.4e38f;
    for (int i = threadIdx.x; i < C; i += TPB) {
        float x = row[i];
        v[cnt++] = x;
        mx = fmaxf(mx, x);
    }
    mx = blockReduceMax(mx, red);
    float s = 0.0f;
    #pragma unroll
    for (int j = 0; j < 4; j++) {
        if (j < cnt) { v[j] = __expf(v[j] - mx); s += v[j]; }
    }
    s = blockReduceSum(s, red);
    float inv = 1.0f / s;
    float* orow = out + (size_t)b * C;
    cnt = 0;
    for (int i = threadIdx.x; i < C; i += TPB) orow[i] = v[cnt++] * inv;
}

// ---------------- center norms ----------------
__global__ void __launch_bounds__(TPB) c2_kernel(const float* __restrict__ Cn, int D)
{
    __shared__ float red[8];
    int c = blockIdx.x;
    const float* row = Cn + (size_t)c * D;
    float s = 0.0f;
    for (int i = threadIdx.x; i < D; i += TPB) { float x = row[i]; s += x * x; }
    s = blockReduceSum(s, red);
    if (threadIdx.x == 0) g_c2[c] = s;
}

// ---------------- int8 IMMA GEMM: s[b,c] = c2[c] - 2 * f_b . c_c ----------------
__device__ __forceinline__ void mma_s8(int* c, const uint32_t* a, const uint32_t* b)
{
    asm volatile(
        "mma.sync.aligned.m16n8k32.row.col.s32.s8.s8.s32 "
        "{%0,%1,%2,%3},{%4,%5,%6,%7},{%8,%9},{%0,%1,%2,%3};\n"
        : "+r"(c[0]), "+r"(c[1]), "+r"(c[2]), "+r"(c[3])
        : "r"(a[0]), "r"(a[1]), "r"(a[2]), "r"(a[3]), "r"(b[0]), "r"(b[1]));
}

// pack 4 floats -> 4 saturated s8 bytes (byte0 = x .. byte3 = w)
__device__ __forceinline__ uint32_t pack_s8(float4 t)
{
    int ix = __float2int_rn(t.x * QSCALE);
    int iy = __float2int_rn(t.y * QSCALE);
    int iz = __float2int_rn(t.z * QSCALE);
    int iw = __float2int_rn(t.w * QSCALE);
    uint32_t t1, r;
    asm("cvt.pack.sat.s8.s32.b32 %0, %1, %2, 0;"  : "=r"(t1) : "r"(iw), "r"(iz));
    asm("cvt.pack.sat.s8.s32.b32 %0, %1, %2, %3;" : "=r"(r)  : "r"(iy), "r"(ix), "r"(t1));
    return r;
}

__global__ void __launch_bounds__(TPB) gemm_mindist_kernel(
    const float* __restrict__ F, const float* __restrict__ Cn,
    int Bsz, int C, int D)
{
    __shared__ uint32_t As[2][BM * STRIDE];   // s8x4 packed, double-buffered
    __shared__ uint32_t Bs[2][BN * STRIDE];

    const int tid  = threadIdx.x;
    const int bm   = blockIdx.y * BM;
    const int bn   = blockIdx.x * BN;
    const int lane = tid & 31;
    const int warp = tid >> 5;
    const int wm   = warp & 3;   // 4 warps in M -> 32 rows each
    const int wn   = warp >> 2;  // 2 warps in N -> 64 cols each
    const int gr   = lane >> 2;
    const int tg   = lane & 3;

    int acc[2][8][4];
    #pragma unroll
    for (int mt = 0; mt < 2; mt++)
        #pragma unroll
        for (int nt = 0; nt < 8; nt++)
            #pragma unroll
            for (int k = 0; k < 4; k++) acc[mt][nt][k] = 0;

    const int nk = D / BK;   // 64
    uint32_t ar[4], br[4];

    auto gload = [&](int kt) {
        #pragma unroll
        for (int j = 0; j < 4; j++) {
            int i  = tid + TPB * j;
            int r  = i >> 3;            // row 0..127
            int c4 = (i & 7) * 4;       // element offset within k-tile
            float4 t = *(const float4*)(F + (size_t)(bm + r) * D + kt * BK + c4);
            ar[j] = pack_s8(t);
            int brow = bn + r;
            if (brow < C) {
                float4 u = *(const float4*)(Cn + (size_t)brow * D + kt * BK + c4);
                br[j] = pack_s8(u);
            } else {
                br[j] = 0u;
            }
        }
    };
    auto sstore = [&](int buf) {
        #pragma unroll
        for (int j = 0; j < 4; j++) {
            int i  = tid + TPB * j;
            int r  = i >> 3;
            int w  = i & 7;             // u32 word within row
            As[buf][r * STRIDE + w] = ar[j];
            Bs[buf][r * STRIDE + w] = br[j];
        }
    };

    gload(0);
    sstore(0);
    __syncthreads();

    for (int kt = 0; kt < nk; kt++) {
        const int buf = kt & 1;
        if (kt + 1 < nk) gload(kt + 1);

        const uint32_t* Ab = &As[buf][(wm * 32) * STRIDE];
        const uint32_t* Bb = &Bs[buf][(wn * 64) * STRIDE];

        // one k=32 mma consumes the whole k-tile: no inner ks loop
        uint32_t a[2][4];
        #pragma unroll
        for (int mt = 0; mt < 2; mt++) {
            a[mt][0] = Ab[(mt * 16 + gr)     * STRIDE + tg];
            a[mt][1] = Ab[(mt * 16 + gr + 8) * STRIDE + tg];
            a[mt][2] = Ab[(mt * 16 + gr)     * STRIDE + tg + 4];
            a[mt][3] = Ab[(mt * 16 + gr + 8) * STRIDE + tg + 4];
        }
        uint32_t bb[8][2];
        #pragma unroll
        for (int nt = 0; nt < 8; nt++) {
            bb[nt][0] = Bb[(nt * 8 + gr) * STRIDE + tg];
            bb[nt][1] = Bb[(nt * 8 + gr) * STRIDE + tg + 4];
        }
        #pragma unroll
        for (int mt = 0; mt < 2; mt++)
            #pragma unroll
            for (int nt = 0; nt < 8; nt++)
                mma_s8(acc[mt][nt], a[mt], bb[nt]);

        if (kt + 1 < nk) {
            sstore(buf ^ 1);   // write other buffer: no hazard with current readers
            __syncthreads();   // single barrier per k-tile
        }
    }

    // epilogue: s = c2[c] - 2 * (idot * (4/127)^2)
    const float two_inv2 = 2.0f * QINV2;
    #pragma unroll
    for (int mt = 0; mt < 2; mt++) {
        #pragma unroll
        for (int nt = 0; nt < 8; nt++) {
            int r0 = bm + wm * 32 + mt * 16 + gr;
            int c0 = bn + wn * 64 + nt * 8 + 2 * tg;
            if (c0 < C) {
                float cc = g_c2[c0];
                g_d2[(size_t)r0 * C + c0]       = cc - two_inv2 * (float)acc[mt][nt][0];
                g_d2[(size_t)(r0 + 8) * C + c0] = cc - two_inv2 * (float)acc[mt][nt][2];
            }
            if (c0 + 1 < C) {
                float cc = g_c2[c0 + 1];
                g_d2[(size_t)r0 * C + c0 + 1]       = cc - two_inv2 * (float)acc[mt][nt][1];
                g_d2[(size_t)(r0 + 8) * C + c0 + 1] = cc - two_inv2 * (float)acc[mt][nt][3];
            }
        }
    }
}

// ---------------- min + exact fp32 refinement + threshold mask ----------------
#define MARGIN 12.0f   // covers ~4 sigma of int8 quantization noise in d2

__global__ void __launch_bounds__(TPB) minmask_kernel(
    const float* __restrict__ F, const float* __restrict__ Cn,
    const float* __restrict__ GS, float* __restrict__ mask, int C, int D)
{
    __shared__ float sfeat[2048];
    __shared__ float red[8];
    __shared__ int   s_cand[64];
    __shared__ int   s_ncand;

    const int b   = blockIdx.x;
    const int tid = threadIdx.x;

    float f2p = 0.0f;
    if ((D & 3) == 0) {
        const float4* F4 = (const float4*)(F + (size_t)b * D);
        for (int i = tid; i < (D >> 2); i += TPB) {
            float4 v = F4[i];
            int k = i * 4;
            sfeat[k] = v.x; sfeat[k+1] = v.y; sfeat[k+2] = v.z; sfeat[k+3] = v.w;
            f2p += v.x*v.x + v.y*v.y + v.z*v.z + v.w*v.w;
        }
    } else {
        for (int i = tid; i < D; i += TPB) {
            float v = F[(size_t)b * D + i];
            sfeat[i] = v;
            f2p += v * v;
        }
    }
    float f2 = blockReduceSum(f2p, red);

    const float* srow = g_d2 + (size_t)b * C;
    float mn = 3.4e38f;
    for (int i = tid; i < C; i += TPB) mn = fminf(mn, srow[i]);
    mn = blockReduceMin(mn, red);

    if (tid == 0) s_ncand = 0;
    __syncthreads();
    for (int i = tid; i < C; i += TPB) {
        if (srow[i] <= mn + MARGIN) {
            int j = atomicAdd(&s_ncand, 1);
            if (j < 64) s_cand[j] = i;
        }
    }
    __syncthreads();
    int nc = min(s_ncand, 64);

    // exact fp32 recompute of candidate distances (kills int8 noise at the decision)
    float best = 3.4e38f;
    for (int j = 0; j < nc; j++) {
        int c = s_cand[j];
        const float* crow = Cn + (size_t)c * D;
        float dp = 0.0f;
        for (int i = tid; i < D; i += TPB) dp += sfeat[i] * crow[i];
        float dot = blockReduceSum(dp, red);
        best = fminf(best, g_c2[c] - 2.0f * dot);
    }

    if (tid == 0) {
        float d2   = f2 + best;
        float dist = sqrtf(fmaxf(d2, 0.0f));
        float T    = GS[0] + 1.5f * GS[1];
        mask[b] = (dist / (T + 1e-8f) > 1.0f) ? 1.0f : 0.0f;
    }
}

__global__ void fill_kernel(float* p, int n)
{
    int i = blockIdx.x * blockDim.x + threadIdx.x;
    if (i < n) p[i] = 0.0f;
}

// ---------------- launch ----------------
extern "C" void kernel_launch(void* const* d_in, const int* in_sizes, int n_in,
                              void* d_out, int out_size)
{
    const float* F  = (const float*)d_in[0];  // features  [B, D]
    const float* P  = (const float*)d_in[1];  // predictions [B, C]
    const float* Cn = (const float*)d_in[2];  // centers [C, D]
    const float* GS = (const float*)d_in[3];  // global_stats [2]

    const int B = in_sizes[4];            // known_labels length
    const int D = in_sizes[0] / B;
    const int C = in_sizes[1] / B;

    float* out   = (float*)d_out;
    float* mask  = out;                   // mask_novel first (return order)
    float* probs = out + B;               // probs second

    softmax_kernel<<<B, TPB>>>(P, probs, C);
    c2_kernel<<<C, TPB>>>(Cn, D);

    dim3 g((C + BN - 1) / BN, B / BM);    // B=16384 divisible by 128; D=2048 by 32
    gemm_mindist_kernel<<<g, TPB>>>(F, Cn, B, C, D);

    minmask_kernel<<<B, TPB>>>(F, Cn, GS, mask, C, D);

    long total = (long)B * C + B;
    if ((long)out_size > total) {
        long rem = (long)out_size - total;
        fill_kernel<<<(int)((rem + 255) / 256), 256>>>(out + total, (int)rem);
    }
}

// round 14
// speedup vs baseline: 2.1872x; 2.1872x over previous
#include <cuda_runtime.h>
#include <cuda_fp16.h>
#include <cstdint>

#define TPB 256
#define BM 128
#define BN 128
#define BK 32
#define STRIDE 20      // 16 data u32 (half2) + 4 pad: fragment LDS bank-conflict-free

// Scratch (no cudaMalloc allowed): s[b,c] = ||center_c||^2 - 2 * f_b . c_c
__device__ float g_d2[16384 * 1000];
__device__ float g_c2[4096];

// ---------------- reductions ----------------
__device__ __forceinline__ float warpReduceSum(float v) {
    #pragma unroll
    for (int o = 16; o > 0; o >>= 1) v += __shfl_xor_sync(0xffffffffu, v, o);
    return v;
}
__device__ __forceinline__ float warpReduceMin(float v) {
    #pragma unroll
    for (int o = 16; o > 0; o >>= 1) v = fminf(v, __shfl_xor_sync(0xffffffffu, v, o));
    return v;
}
__device__ __forceinline__ float warpReduceMax(float v) {
    #pragma unroll
    for (int o = 16; o > 0; o >>= 1) v = fmaxf(v, __shfl_xor_sync(0xffffffffu, v, o));
    return v;
}
__device__ __forceinline__ float blockReduceSum(float v, float* red) {
    __syncthreads();
    v = warpReduceSum(v);
    int w = threadIdx.x >> 5, l = threadIdx.x & 31;
    if (l == 0) red[w] = v;
    __syncthreads();
    if (w == 0) {
        float x = (l < (int)(blockDim.x >> 5)) ? red[l] : 0.0f;
        x = warpReduceSum(x);
        if (l == 0) red[0] = x;
    }
    __syncthreads();
    return red[0];
}
__device__ __forceinline__ float blockReduceMin(float v, float* red) {
    __syncthreads();
    v = warpReduceMin(v);
    int w = threadIdx.x >> 5, l = threadIdx.x & 31;
    if (l == 0) red[w] = v;
    __syncthreads();
    if (w == 0) {
        float x = (l < (int)(blockDim.x >> 5)) ? red[l] : 3.4e38f;
        x = warpReduceMin(x);
        if (l == 0) red[0] = x;
    }
    __syncthreads();
    return red[0];
}
__device__ __forceinline__ float blockReduceMax(float v, float* red) {
    __syncthreads();
    v = warpReduceMax(v);
    int w = threadIdx.x >> 5, l = threadIdx.x & 31;
    if (l == 0) red[w] = v;
    __syncthreads();
    if (w == 0) {
        float x = (l < (int)(blockDim.x >> 5)) ? red[l] : -3.4e38f;
        x = warpReduceMax(x);
        if (l == 0) red[0] = x;
    }
    __syncthreads();
    return red[0];
}

// ---------------- softmax over classes ----------------
__global__ void __launch_bounds__(TPB) softmax_kernel(
    const float* __restrict__ P, float* __restrict__ out, int C)
{
    __shared__ float red[8];
    int b = blockIdx.x;
    const float* row = P + (size_t)b * C;
    float v[4];
    int cnt = 0;
    float mx = -3.4e38f;
    for (int i = threadIdx.x; i < C; i += TPB) {
        float x = row[i];
        v[cnt++] = x;
        mx = fmaxf(mx, x);
    }
    mx = blockReduceMax(mx, red);
    float s = 0.0f;
    #pragma unroll
    for (int j = 0; j < 4; j++) {
        if (j < cnt) { v[j] = __expf(v[j] - mx); s += v[j]; }
    }
    s = blockReduceSum(s, red);
    float inv = 1.0f / s;
    float* orow = out + (size_t)b * C;
    cnt = 0;
    for (int i = threadIdx.x; i < C; i += TPB) orow[i] = v[cnt++] * inv;
}

// ---------------- center norms ----------------
__global__ void __launch_bounds__(TPB) c2_kernel(const float* __restrict__ Cn, int D)
{
    __shared__ float red[8];
    int c = blockIdx.x;
    const float* row = Cn + (size_t)c * D;
    float s = 0.0f;
    for (int i = threadIdx.x; i < D; i += TPB) { float x = row[i]; s += x * x; }
    s = blockReduceSum(s, red);
    if (threadIdx.x == 0) g_c2[c] = s;
}

// ---------------- fp16 mma (fp16 accumulate): s[b,c] = c2[c] - 2 * f_b . c_c ----------------
__device__ __forceinline__ void mma_f16acc(uint32_t* c, const uint32_t* a, const uint32_t* b)
{
    asm volatile(
        "mma.sync.aligned.m16n8k16.row.col.f16.f16.f16.f16 "
        "{%0,%1},{%2,%3,%4,%5},{%6,%7},{%0,%1};\n"
        : "+r"(c[0]), "+r"(c[1])
        : "r"(a[0]), "r"(a[1]), "r"(a[2]), "r"(a[3]), "r"(b[0]), "r"(b[1]));
}

__device__ __forceinline__ uint32_t pack_h16(float x, float y)
{
    __half2 h = __float22half2_rn(make_float2(x, y));
    return *reinterpret_cast<uint32_t*>(&h);
}

__global__ void __launch_bounds__(TPB) gemm_mindist_kernel(
    const float* __restrict__ F, const float* __restrict__ Cn,
    int Bsz, int C, int D)
{
    __shared__ uint32_t As[2][BM * STRIDE];   // half2 packed, double-buffered
    __shared__ uint32_t Bs[2][BN * STRIDE];

    const int tid  = threadIdx.x;
    const int bm   = blockIdx.y * BM;
    const int bn   = blockIdx.x * BN;
    const int lane = tid & 31;
    const int warp = tid >> 5;
    const int wm   = warp & 3;   // 4 warps in M -> 32 rows each
    const int wn   = warp >> 2;  // 2 warps in N -> 64 cols each
    const int gr   = lane >> 2;
    const int tg   = lane & 3;

    // two accumulators per tile (one per ks) -> shorter fp16 accumulation chains
    uint32_t acc[2][2][8][2];
    #pragma unroll
    for (int ks = 0; ks < 2; ks++)
        #pragma unroll
        for (int mt = 0; mt < 2; mt++)
            #pragma unroll
            for (int nt = 0; nt < 8; nt++) {
                acc[ks][mt][nt][0] = 0u;
                acc[ks][mt][nt][1] = 0u;
            }

    const int nk = D / BK;   // 64
    uint2 ar[4], br[4];

    auto gload = [&](int kt) {
        #pragma unroll
        for (int j = 0; j < 4; j++) {
            int i  = tid + TPB * j;
            int r  = i >> 3;
            int c4 = (i & 7) * 4;
            float4 t = *(const float4*)(F + (size_t)(bm + r) * D + kt * BK + c4);
            ar[j].x = pack_h16(t.x, t.y);
            ar[j].y = pack_h16(t.z, t.w);
            int brow = bn + r;
            if (brow < C) {
                float4 u = *(const float4*)(Cn + (size_t)brow * D + kt * BK + c4);
                br[j].x = pack_h16(u.x, u.y);
                br[j].y = pack_h16(u.z, u.w);
            } else {
                br[j].x = 0u; br[j].y = 0u;
            }
        }
    };
    auto sstore = [&](int buf) {
        #pragma unroll
        for (int j = 0; j < 4; j++) {
            int i  = tid + TPB * j;
            int r  = i >> 3;
            int k2 = (i & 7) * 2;
            *(uint2*)&As[buf][r * STRIDE + k2] = ar[j];
            *(uint2*)&Bs[buf][r * STRIDE + k2] = br[j];
        }
    };

    gload(0);
    sstore(0);
    __syncthreads();

    for (int kt = 0; kt < nk; kt++) {
        const int buf = kt & 1;
        if (kt + 1 < nk) gload(kt + 1);

        const uint32_t* Ab = &As[buf][(wm * 32) * STRIDE];
        const uint32_t* Bb = &Bs[buf][(wn * 64) * STRIDE];

        #pragma unroll
        for (int ks = 0; ks < 2; ks++) {
            const int off = ks * 8;
            uint32_t a[2][4];
            #pragma unroll
            for (int mt = 0; mt < 2; mt++) {
                a[mt][0] = Ab[(mt * 16 + gr)     * STRIDE + off + tg];
                a[mt][1] = Ab[(mt * 16 + gr + 8) * STRIDE + off + tg];
                a[mt][2] = Ab[(mt * 16 + gr)     * STRIDE + off + tg + 4];
                a[mt][3] = Ab[(mt * 16 + gr + 8) * STRIDE + off + tg + 4];
            }
            uint32_t bb[8][2];
            #pragma unroll
            for (int nt = 0; nt < 8; nt++) {
                bb[nt][0] = Bb[(nt * 8 + gr) * STRIDE + off + tg];
                bb[nt][1] = Bb[(nt * 8 + gr) * STRIDE + off + tg + 4];
            }
            #pragma unroll
            for (int mt = 0; mt < 2; mt++)
                #pragma unroll
                for (int nt = 0; nt < 8; nt++)
                    mma_f16acc(acc[ks][mt][nt], a[mt], bb[nt]);
        }

        if (kt + 1 < nk) {
            sstore(buf ^ 1);   // write other buffer: no hazard with current readers
            __syncthreads();   // single barrier per k-tile
        }
    }

    // epilogue: s = c2[c] - 2*(cross_ks0 + cross_ks1), fp16 pairs -> fp32
    // f16-acc D layout: c[0] = halves {(gr,2tg),(gr,2tg+1)}, c[1] = {(gr+8,2tg),(gr+8,2tg+1)}
    #pragma unroll
    for (int mt = 0; mt < 2; mt++) {
        #pragma unroll
        for (int nt = 0; nt < 8; nt++) {
            float2 l0 = __half22float2(*reinterpret_cast<__half2*>(&acc[0][mt][nt][0]));
            float2 h0 = __half22float2(*reinterpret_cast<__half2*>(&acc[0][mt][nt][1]));
            float2 l1 = __half22float2(*reinterpret_cast<__half2*>(&acc[1][mt][nt][0]));
            float2 h1 = __half22float2(*reinterpret_cast<__half2*>(&acc[1][mt][nt][1]));
            int r0 = bm + wm * 32 + mt * 16 + gr;
            int c0 = bn + wn * 64 + nt * 8 + 2 * tg;
            if (c0 < C) {
                float cc = g_c2[c0];
                g_d2[(size_t)r0 * C + c0]       = cc - 2.0f * (l0.x + l1.x);
                g_d2[(size_t)(r0 + 8) * C + c0] = cc - 2.0f * (h0.x + h1.x);
            }
            if (c0 + 1 < C) {
                float cc = g_c2[c0 + 1];
                g_d2[(size_t)r0 * C + c0 + 1]       = cc - 2.0f * (l0.y + l1.y);
                g_d2[(size_t)(r0 + 8) * C + c0 + 1] = cc - 2.0f * (h0.y + h1.y);
            }
        }
    }
}

// ---------------- min + exact fp32 refinement + threshold mask ----------------
#define MARGIN 8.0f    // ~5 sigma of fp16-accumulation noise in d2

__global__ void __launch_bounds__(TPB) minmask_kernel(
    const float* __restrict__ F, const float* __restrict__ Cn,
    const float* __restrict__ GS, float* __restrict__ mask, int C, int D)
{
    __shared__ float sfeat[2048];
    __shared__ float red[8];
    __shared__ int   s_cand[64];
    __shared__ int   s_ncand;

    const int b   = blockIdx.x;
    const int tid = threadIdx.x;

    float f2p = 0.0f;
    if ((D & 3) == 0) {
        const float4* F4 = (const float4*)(F + (size_t)b * D);
        for (int i = tid; i < (D >> 2); i += TPB) {
            float4 v = F4[i];
            int k = i * 4;
            sfeat[k] = v.x; sfeat[k+1] = v.y; sfeat[k+2] = v.z; sfeat[k+3] = v.w;
            f2p += v.x*v.x + v.y*v.y + v.z*v.z + v.w*v.w;
        }
    } else {
        for (int i = tid; i < D; i += TPB) {
            float v = F[(size_t)b * D + i];
            sfeat[i] = v;
            f2p += v * v;
        }
    }
    float f2 = blockReduceSum(f2p, red);

    const float* srow = g_d2 + (size_t)b * C;
    float mn = 3.4e38f;
    for (int i = tid; i < C; i += TPB) mn = fminf(mn, srow[i]);
    mn = blockReduceMin(mn, red);

    if (tid == 0) s_ncand = 0;
    __syncthreads();
    for (int i = tid; i < C; i += TPB) {
        if (srow[i] <= mn + MARGIN) {
            int j = atomicAdd(&s_ncand, 1);
            if (j < 64) s_cand[j] = i;
        }
    }
    __syncthreads();
    int nc = min(s_ncand, 64);

    // exact fp32 recompute of candidate distances (kills fp16 noise at the decision)
    float best = 3.4e38f;
    for (int j = 0; j < nc; j++) {
        int c = s_cand[j];
        const float* crow = Cn + (size_t)c * D;
        float dp = 0.0f;
        for (int i = tid; i < D; i += TPB) dp += sfeat[i] * crow[i];
        float dot = blockReduceSum(dp, red);
        best = fminf(best, g_c2[c] - 2.0f * dot);
    }

    if (tid == 0) {
        float d2   = f2 + best;
        float dist = sqrtf(fmaxf(d2, 0.0f));
        float T    = GS[0] + 1.5f * GS[1];
        mask[b] = (dist / (T + 1e-8f) > 1.0f) ? 1.0f : 0.0f;
    }
}

__global__ void fill_kernel(float* p, int n)
{
    int i = blockIdx.x * blockDim.x + threadIdx.x;
    if (i < n) p[i] = 0.0f;
}

// ---------------- launch ----------------
extern "C" void kernel_launch(void* const* d_in, const int* in_sizes, int n_in,
                              void* d_out, int out_size)
{
    const float* F  = (const float*)d_in[0];  // features  [B, D]
    const float* P  = (const float*)d_in[1];  // predictions [B, C]
    const float* Cn = (const float*)d_in[2];  // centers [C, D]
    const float* GS = (const float*)d_in[3];  // global_stats [2]

    const int B = in_sizes[4];            // known_labels length
    const int D = in_sizes[0] / B;
    const int C = in_sizes[1] / B;

    float* out   = (float*)d_out;
    float* mask  = out;                   // mask_novel first (return order)
    float* probs = out + B;               // probs second

    softmax_kernel<<<B, TPB>>>(P, probs, C);
    c2_kernel<<<C, TPB>>>(Cn, D);

    dim3 g((C + BN - 1) / BN, B / BM);    // B=16384 divisible by 128; D=2048 by 32
    gemm_mindist_kernel<<<g, TPB>>>(F, Cn, B, C, D);

    minmask_kernel<<<B, TPB>>>(F, Cn, GS, mask, C, D);

    long total = (long)B * C + B;
    if ((long)out_size > total) {
        long rem = (long)out_size - total;
        fill_kernel<<<(int)((rem + 255) / 256), 256>>>(out + total, (int)rem);
    }
}

// round 15
// speedup vs baseline: 2.4038x; 1.0990x over previous
#include <cuda_runtime.h>
#include <cuda_fp16.h>
#include <cstdint>

#define TPB 256
#define BM 128
#define BN 128
#define BK 32
#define STRIDE 20      // 16 data u32 (half2) + 4 pad: fragment LDS bank-conflict-free

// Scratch (no cudaMalloc allowed)
__device__ float g_d2[16384 * 1000];
__device__ float g_c2[4096];
__device__ __half g_Fh[16384 * 2048];
__device__ __half g_Ch[1024 * 2048];    // centers padded to 1024 rows (zeros)

// ---------------- reductions ----------------
__device__ __forceinline__ float warpReduceSum(float v) {
    #pragma unroll
    for (int o = 16; o > 0; o >>= 1) v += __shfl_xor_sync(0xffffffffu, v, o);
    return v;
}
__device__ __forceinline__ float warpReduceMin(float v) {
    #pragma unroll
    for (int o = 16; o > 0; o >>= 1) v = fminf(v, __shfl_xor_sync(0xffffffffu, v, o));
    return v;
}
__device__ __forceinline__ float warpReduceMax(float v) {
    #pragma unroll
    for (int o = 16; o > 0; o >>= 1) v = fmaxf(v, __shfl_xor_sync(0xffffffffu, v, o));
    return v;
}
__device__ __forceinline__ float blockReduceSum(float v, float* red) {
    __syncthreads();
    v = warpReduceSum(v);
    int w = threadIdx.x >> 5, l = threadIdx.x & 31;
    if (l == 0) red[w] = v;
    __syncthreads();
    if (w == 0) {
        float x = (l < (int)(blockDim.x >> 5)) ? red[l] : 0.0f;
        x = warpReduceSum(x);
        if (l == 0) red[0] = x;
    }
    __syncthreads();
    return red[0];
}
__device__ __forceinline__ float blockReduceMin(float v, float* red) {
    __syncthreads();
    v = warpReduceMin(v);
    int w = threadIdx.x >> 5, l = threadIdx.x & 31;
    if (l == 0) red[w] = v;
    __syncthreads();
    if (w == 0) {
        float x = (l < (int)(blockDim.x >> 5)) ? red[l] : 3.4e38f;
        x = warpReduceMin(x);
        if (l == 0) red[0] = x;
    }
    __syncthreads();
    return red[0];
}
__device__ __forceinline__ float blockReduceMax(float v, float* red) {
    __syncthreads();
    v = warpReduceMax(v);
    int w = threadIdx.x >> 5, l = threadIdx.x & 31;
    if (l == 0) red[w] = v;
    __syncthreads();
    if (w == 0) {
        float x = (l < (int)(blockDim.x >> 5)) ? red[l] : -3.4e38f;
        x = warpReduceMax(x);
        if (l == 0) red[0] = x;
    }
    __syncthreads();
    return red[0];
}

// ---------------- softmax over classes ----------------
__global__ void __launch_bounds__(TPB) softmax_kernel(
    const float* __restrict__ P, float* __restrict__ out, int C)
{
    __shared__ float red[8];
    int b = blockIdx.x;
    const float* row = P + (size_t)b * C;
    float v[4];
    int cnt = 0;
    float mx = -3.4e38f;
    for (int i = threadIdx.x; i < C; i += TPB) {
        float x = row[i];
        v[cnt++] = x;
        mx = fmaxf(mx, x);
    }
    mx = blockReduceMax(mx, red);
    float s = 0.0f;
    #pragma unroll
    for (int j = 0; j < 4; j++) {
        if (j < cnt) { v[j] = __expf(v[j] - mx); s += v[j]; }
    }
    s = blockReduceSum(s, red);
    float inv = 1.0f / s;
    float* orow = out + (size_t)b * C;
    cnt = 0;
    for (int i = threadIdx.x; i < C; i += TPB) orow[i] = v[cnt++] * inv;
}

// ---------------- center norms ----------------
__global__ void __launch_bounds__(TPB) c2_kernel(const float* __restrict__ Cn, int D)
{
    __shared__ float red[8];
    int c = blockIdx.x;
    const float* row = Cn + (size_t)c * D;
    float s = 0.0f;
    for (int i = threadIdx.x; i < D; i += TPB) { float x = row[i]; s += x * x; }
    s = blockReduceSum(s, red);
    if (threadIdx.x == 0) g_c2[c] = s;
}

// ---------------- fp32 -> fp16 pre-conversion (F and padded centers) ----------------
__device__ __forceinline__ uint32_t pack_h16(float x, float y)
{
    __half2 h = __float22half2_rn(make_float2(x, y));
    return *reinterpret_cast<uint32_t*>(&h);
}

__global__ void __launch_bounds__(TPB) cvt_kernel(
    const float* __restrict__ F, const float* __restrict__ Cn,
    int nF8, int C, int D)
{
    int i = blockIdx.x * blockDim.x + threadIdx.x;
    int nC8 = (1024 * D) >> 3;
    if (i < nF8) {
        const float4* src = (const float4*)F + (size_t)i * 2;
        float4 a = src[0], b = src[1];
        uint4 v;
        v.x = pack_h16(a.x, a.y); v.y = pack_h16(a.z, a.w);
        v.z = pack_h16(b.x, b.y); v.w = pack_h16(b.z, b.w);
        ((uint4*)g_Fh)[i] = v;
    } else {
        int j = i - nF8;
        if (j < nC8) {
            int row = (j * 8) / D;
            uint4 v = make_uint4(0u, 0u, 0u, 0u);
            if (row < C) {
                const float4* src = (const float4*)Cn + (size_t)j * 2;
                float4 a = src[0], b = src[1];
                v.x = pack_h16(a.x, a.y); v.y = pack_h16(a.z, a.w);
                v.z = pack_h16(b.x, b.y); v.w = pack_h16(b.z, b.w);
            }
            ((uint4*)g_Ch)[j] = v;
        }
    }
}

// ---------------- fp16 mma (fp16 accumulate): s[b,c] = c2[c] - 2 * f_b . c_c ----------------
__device__ __forceinline__ void mma_f16acc(uint32_t* c, const uint32_t* a, const uint32_t* b)
{
    asm volatile(
        "mma.sync.aligned.m16n8k16.row.col.f16.f16.f16.f16 "
        "{%0,%1},{%2,%3,%4,%5},{%6,%7},{%0,%1};\n"
        : "+r"(c[0]), "+r"(c[1])
        : "r"(a[0]), "r"(a[1]), "r"(a[2]), "r"(a[3]), "r"(b[0]), "r"(b[1]));
}

__global__ void __launch_bounds__(TPB) gemm_mindist_kernel(int C, int D)
{
    __shared__ uint32_t As[2][BM * STRIDE];   // half2 packed, double-buffered
    __shared__ uint32_t Bs[2][BN * STRIDE];

    const int tid  = threadIdx.x;
    const int bm   = blockIdx.y * BM;
    const int bn   = blockIdx.x * BN;
    const int lane = tid & 31;
    const int warp = tid >> 5;
    const int wm   = warp & 3;   // 4 warps in M -> 32 rows each
    const int wn   = warp >> 2;  // 2 warps in N -> 64 cols each
    const int gr   = lane >> 2;
    const int tg   = lane & 3;

    // two accumulators per tile (one per ks) -> shorter fp16 accumulation chains
    uint32_t acc[2][2][8][2];
    #pragma unroll
    for (int ks = 0; ks < 2; ks++)
        #pragma unroll
        for (int mt = 0; mt < 2; mt++)
            #pragma unroll
            for (int nt = 0; nt < 8; nt++) {
                acc[ks][mt][nt][0] = 0u;
                acc[ks][mt][nt][1] = 0u;
            }

    const int nk = D / BK;   // 64
    uint4 ar[2], br[2];

    // fp16 data, ready to use: 4x LDG.128 per thread per k-tile total (2 A + 2 B)
    auto gload = [&](int kt) {
        #pragma unroll
        for (int j = 0; j < 2; j++) {
            int i  = tid + TPB * j;     // 0..511
            int r  = i >> 2;            // row 0..127
            int ch = i & 3;             // 8-half chunk within 32-col k-tile
            ar[j] = *(const uint4*)(g_Fh + (size_t)(bm + r) * D + kt * BK + ch * 8);
            br[j] = *(const uint4*)(g_Ch + (size_t)(bn + r) * D + kt * BK + ch * 8);
        }
    };
    auto sstore = [&](int buf) {
        #pragma unroll
        for (int j = 0; j < 2; j++) {
            int i  = tid + TPB * j;
            int r  = i >> 2;
            int ch = i & 3;
            *(uint4*)&As[buf][r * STRIDE + ch * 4] = ar[j];
            *(uint4*)&Bs[buf][r * STRIDE + ch * 4] = br[j];
        }
    };

    gload(0);
    sstore(0);
    __syncthreads();

    for (int kt = 0; kt < nk; kt++) {
        const int buf = kt & 1;
        if (kt + 1 < nk) gload(kt + 1);

        const uint32_t* Ab = &As[buf][(wm * 32) * STRIDE];
        const uint32_t* Bb = &Bs[buf][(wn * 64) * STRIDE];

        #pragma unroll
        for (int ks = 0; ks < 2; ks++) {
            const int off = ks * 8;
            uint32_t a[2][4];
            #pragma unroll
            for (int mt = 0; mt < 2; mt++) {
                a[mt][0] = Ab[(mt * 16 + gr)     * STRIDE + off + tg];
                a[mt][1] = Ab[(mt * 16 + gr + 8) * STRIDE + off + tg];
                a[mt][2] = Ab[(mt * 16 + gr)     * STRIDE + off + tg + 4];
                a[mt][3] = Ab[(mt * 16 + gr + 8) * STRIDE + off + tg + 4];
            }
            uint32_t bb[8][2];
            #pragma unroll
            for (int nt = 0; nt < 8; nt++) {
                bb[nt][0] = Bb[(nt * 8 + gr) * STRIDE + off + tg];
                bb[nt][1] = Bb[(nt * 8 + gr) * STRIDE + off + tg + 4];
            }
            #pragma unroll
            for (int mt = 0; mt < 2; mt++)
                #pragma unroll
                for (int nt = 0; nt < 8; nt++)
                    mma_f16acc(acc[ks][mt][nt], a[mt], bb[nt]);
        }

        if (kt + 1 < nk) {
            sstore(buf ^ 1);   // write other buffer: no hazard with current readers
            __syncthreads();   // single barrier per k-tile
        }
    }

    // epilogue: s = c2[c] - 2*(cross_ks0 + cross_ks1), fp16 pairs -> fp32
    #pragma unroll
    for (int mt = 0; mt < 2; mt++) {
        #pragma unroll
        for (int nt = 0; nt < 8; nt++) {
            float2 l0 = __half22float2(*reinterpret_cast<__half2*>(&acc[0][mt][nt][0]));
            float2 h0 = __half22float2(*reinterpret_cast<__half2*>(&acc[0][mt][nt][1]));
            float2 l1 = __half22float2(*reinterpret_cast<__half2*>(&acc[1][mt][nt][0]));
            float2 h1 = __half22float2(*reinterpret_cast<__half2*>(&acc[1][mt][nt][1]));
            int r0 = bm + wm * 32 + mt * 16 + gr;
            int c0 = bn + wn * 64 + nt * 8 + 2 * tg;
            if (c0 < C) {
                float cc = g_c2[c0];
                g_d2[(size_t)r0 * C + c0]       = cc - 2.0f * (l0.x + l1.x);
                g_d2[(size_t)(r0 + 8) * C + c0] = cc - 2.0f * (h0.x + h1.x);
            }
            if (c0 + 1 < C) {
                float cc = g_c2[c0 + 1];
                g_d2[(size_t)r0 * C + c0 + 1]       = cc - 2.0f * (l0.y + l1.y);
                g_d2[(size_t)(r0 + 8) * C + c0 + 1] = cc - 2.0f * (h0.y + h1.y);
            }
        }
    }
}

// ---------------- min + exact fp32 refinement + threshold mask ----------------
#define MARGIN 8.0f    // ~5 sigma of fp16 accumulation + input-quantization noise in d2

__global__ void __launch_bounds__(TPB) minmask_kernel(
    const float* __restrict__ F, const float* __restrict__ Cn,
    const float* __restrict__ GS, float* __restrict__ mask, int C, int D)
{
    __shared__ float sfeat[2048];
    __shared__ float red[8];
    __shared__ int   s_cand[64];
    __shared__ int   s_ncand;

    const int b   = blockIdx.x;
    const int tid = threadIdx.x;

    float f2p = 0.0f;
    if ((D & 3) == 0) {
        const float4* F4 = (const float4*)(F + (size_t)b * D);
        for (int i = tid; i < (D >> 2); i += TPB) {
            float4 v = F4[i];
            int k = i * 4;
            sfeat[k] = v.x; sfeat[k+1] = v.y; sfeat[k+2] = v.z; sfeat[k+3] = v.w;
            f2p += v.x*v.x + v.y*v.y + v.z*v.z + v.w*v.w;
        }
    } else {
        for (int i = tid; i < D; i += TPB) {
            float v = F[(size_t)b * D + i];
            sfeat[i] = v;
            f2p += v * v;
        }
    }
    float f2 = blockReduceSum(f2p, red);

    const float* srow = g_d2 + (size_t)b * C;
    float mn = 3.4e38f;
    for (int i = tid; i < C; i += TPB) mn = fminf(mn, srow[i]);
    mn = blockReduceMin(mn, red);

    if (tid == 0) s_ncand = 0;
    __syncthreads();
    for (int i = tid; i < C; i += TPB) {
        if (srow[i] <= mn + MARGIN) {
            int j = atomicAdd(&s_ncand, 1);
            if (j < 64) s_cand[j] = i;
        }
    }
    __syncthreads();
    int nc = min(s_ncand, 64);

    // exact fp32 recompute of candidate distances (kills fp16 noise at the decision)
    float best = 3.4e38f;
    for (int j = 0; j < nc; j++) {
        int c = s_cand[j];
        const float* crow = Cn + (size_t)c * D;
        float dp = 0.0f;
        for (int i = tid; i < D; i += TPB) dp += sfeat[i] * crow[i];
        float dot = blockReduceSum(dp, red);
        best = fminf(best, g_c2[c] - 2.0f * dot);
    }

    if (tid == 0) {
        float d2   = f2 + best;
        float dist = sqrtf(fmaxf(d2, 0.0f));
        float T    = GS[0] + 1.5f * GS[1];
        mask[b] = (dist / (T + 1e-8f) > 1.0f) ? 1.0f : 0.0f;
    }
}

__global__ void fill_kernel(float* p, int n)
{
    int i = blockIdx.x * blockDim.x + threadIdx.x;
    if (i < n) p[i] = 0.0f;
}

// ---------------- launch ----------------
extern "C" void kernel_launch(void* const* d_in, const int* in_sizes, int n_in,
                              void* d_out, int out_size)
{
    const float* F  = (const float*)d_in[0];  // features  [B, D]
    const float* P  = (const float*)d_in[1];  // predictions [B, C]
    const float* Cn = (const float*)d_in[2];  // centers [C, D]
    const float* GS = (const float*)d_in[3];  // global_stats [2]

    const int B = in_sizes[4];            // known_labels length
    const int D = in_sizes[0] / B;
    const int C = in_sizes[1] / B;

    float* out   = (float*)d_out;
    float* mask  = out;                   // mask_novel first (return order)
    float* probs = out + B;               // probs second

    softmax_kernel<<<B, TPB>>>(P, probs, C);
    c2_kernel<<<C, TPB>>>(Cn, D);

    int nF8 = (B * D) >> 3;
    int nC8 = (1024 * D) >> 3;
    cvt_kernel<<<(nF8 + nC8 + TPB - 1) / TPB, TPB>>>(F, Cn, nF8, C, D);

    dim3 g((C + BN - 1) / BN, B / BM);    // B=16384 divisible by 128; D=2048 by 32
    gemm_mindist_kernel<<<g, TPB>>>(C, D);

    minmask_kernel<<<B, TPB>>>(F, Cn, GS, mask, C, D);

    long total = (long)B * C + B;
    if ((long)out_size > total) {
        long rem = (long)out_size - total;
        fill_kernel<<<(int)((rem + 255) / 256), 256>>>(out + total, (int)rem);
    }
}

// round 16
// speedup vs baseline: 2.5963x; 1.0801x over previous
#include <cuda_runtime.h>
#include <cuda_fp16.h>
#include <cstdint>

#define TPB 256
#define BM 128
#define BN 128
#define BK 32
#define STRIDE 20      // 16 data u32 (half2) + 4 pad: LDSM row phases hit all 32 banks

// Scratch (no cudaMalloc allowed)
__device__ float g_d2[16384 * 1000];
__device__ float g_c2[4096];
__device__ __half g_Fh[16384 * 2048];
__device__ __half g_Ch[1024 * 2048];    // centers padded to 1024 rows (zeros)

// ---------------- reductions ----------------
__device__ __forceinline__ float warpReduceSum(float v) {
    #pragma unroll
    for (int o = 16; o > 0; o >>= 1) v += __shfl_xor_sync(0xffffffffu, v, o);
    return v;
}
__device__ __forceinline__ float warpReduceMin(float v) {
    #pragma unroll
    for (int o = 16; o > 0; o >>= 1) v = fminf(v, __shfl_xor_sync(0xffffffffu, v, o));
    return v;
}
__device__ __forceinline__ float warpReduceMax(float v) {
    #pragma unroll
    for (int o = 16; o > 0; o >>= 1) v = fmaxf(v, __shfl_xor_sync(0xffffffffu, v, o));
    return v;
}
__device__ __forceinline__ float blockReduceSum(float v, float* red) {
    __syncthreads();
    v = warpReduceSum(v);
    int w = threadIdx.x >> 5, l = threadIdx.x & 31;
    if (l == 0) red[w] = v;
    __syncthreads();
    if (w == 0) {
        float x = (l < (int)(blockDim.x >> 5)) ? red[l] : 0.0f;
        x = warpReduceSum(x);
        if (l == 0) red[0] = x;
    }
    __syncthreads();
    return red[0];
}
__device__ __forceinline__ float blockReduceMin(float v, float* red) {
    __syncthreads();
    v = warpReduceMin(v);
    int w = threadIdx.x >> 5, l = threadIdx.x & 31;
    if (l == 0) red[w] = v;
    __syncthreads();
    if (w == 0) {
        float x = (l < (int)(blockDim.x >> 5)) ? red[l] : 3.4e38f;
        x = warpReduceMin(x);
        if (l == 0) red[0] = x;
    }
    __syncthreads();
    return red[0];
}
__device__ __forceinline__ float blockReduceMax(float v, float* red) {
    __syncthreads();
    v = warpReduceMax(v);
    int w = threadIdx.x >> 5, l = threadIdx.x & 31;
    if (l == 0) red[w] = v;
    __syncthreads();
    if (w == 0) {
        float x = (l < (int)(blockDim.x >> 5)) ? red[l] : -3.4e38f;
        x = warpReduceMax(x);
        if (l == 0) red[0] = x;
    }
    __syncthreads();
    return red[0];
}

// ---------------- softmax over classes ----------------
__global__ void __launch_bounds__(TPB) softmax_kernel(
    const float* __restrict__ P, float* __restrict__ out, int C)
{
    __shared__ float red[8];
    int b = blockIdx.x;
    const float* row = P + (size_t)b * C;
    float v[4];
    int cnt = 0;
    float mx = -3.4e38f;
    for (int i = threadIdx.x; i < C; i += TPB) {
        float x = row[i];
        v[cnt++] = x;
        mx = fmaxf(mx, x);
    }
    mx = blockReduceMax(mx, red);
    float s = 0.0f;
    #pragma unroll
    for (int j = 0; j < 4; j++) {
        if (j < cnt) { v[j] = __expf(v[j] - mx); s += v[j]; }
    }
    s = blockReduceSum(s, red);
    float inv = 1.0f / s;
    float* orow = out + (size_t)b * C;
    cnt = 0;
    for (int i = threadIdx.x; i < C; i += TPB) orow[i] = v[cnt++] * inv;
}

// ---------------- center norms ----------------
__global__ void __launch_bounds__(TPB) c2_kernel(const float* __restrict__ Cn, int D)
{
    __shared__ float red[8];
    int c = blockIdx.x;
    const float* row = Cn + (size_t)c * D;
    float s = 0.0f;
    for (int i = threadIdx.x; i < D; i += TPB) { float x = row[i]; s += x * x; }
    s = blockReduceSum(s, red);
    if (threadIdx.x == 0) g_c2[c] = s;
}

// ---------------- fp32 -> fp16 pre-conversion (F and padded centers) ----------------
__device__ __forceinline__ uint32_t pack_h16(float x, float y)
{
    __half2 h = __float22half2_rn(make_float2(x, y));
    return *reinterpret_cast<uint32_t*>(&h);
}

__global__ void __launch_bounds__(TPB) cvt_kernel(
    const float* __restrict__ F, const float* __restrict__ Cn,
    int nF8, int C, int D)
{
    int i = blockIdx.x * blockDim.x + threadIdx.x;
    int nC8 = (1024 * D) >> 3;
    if (i < nF8) {
        const float4* src = (const float4*)F + (size_t)i * 2;
        float4 a = src[0], b = src[1];
        uint4 v;
        v.x = pack_h16(a.x, a.y); v.y = pack_h16(a.z, a.w);
        v.z = pack_h16(b.x, b.y); v.w = pack_h16(b.z, b.w);
        ((uint4*)g_Fh)[i] = v;
    } else {
        int j = i - nF8;
        if (j < nC8) {
            int row = (j * 8) / D;
            uint4 v = make_uint4(0u, 0u, 0u, 0u);
            if (row < C) {
                const float4* src = (const float4*)Cn + (size_t)j * 2;
                float4 a = src[0], b = src[1];
                v.x = pack_h16(a.x, a.y); v.y = pack_h16(a.z, a.w);
                v.z = pack_h16(b.x, b.y); v.w = pack_h16(b.z, b.w);
            }
            ((uint4*)g_Ch)[j] = v;
        }
    }
}

// ---------------- fp16 mma (fp16 accumulate) + ldmatrix fragment loads ----------------
__device__ __forceinline__ void mma_f16acc(uint32_t* c, const uint32_t* a, const uint32_t* b)
{
    asm volatile(
        "mma.sync.aligned.m16n8k16.row.col.f16.f16.f16.f16 "
        "{%0,%1},{%2,%3,%4,%5},{%6,%7},{%0,%1};\n"
        : "+r"(c[0]), "+r"(c[1])
        : "r"(a[0]), "r"(a[1]), "r"(a[2]), "r"(a[3]), "r"(b[0]), "r"(b[1]));
}

__device__ __forceinline__ void ldsm_x4(uint32_t* r, uint32_t addr)
{
    asm volatile("ldmatrix.sync.aligned.m8n8.x4.shared.b16 {%0,%1,%2,%3}, [%4];"
        : "=r"(r[0]), "=r"(r[1]), "=r"(r[2]), "=r"(r[3]) : "r"(addr));
}

__device__ __forceinline__ uint32_t smem_u32(const void* p)
{
    uint32_t a;
    asm("{ .reg .u64 t; cvta.to.shared.u64 t, %1; cvt.u32.u64 %0, t; }" : "=r"(a) : "l"(p));
    return a;
}

__global__ void __launch_bounds__(TPB) gemm_mindist_kernel(int C, int D)
{
    __shared__ uint32_t As[2][BM * STRIDE];   // half2 packed, double-buffered
    __shared__ uint32_t Bs[2][BN * STRIDE];

    const int tid  = threadIdx.x;
    const int bm   = blockIdx.y * BM;
    const int bn   = blockIdx.x * BN;
    const int lane = tid & 31;
    const int warp = tid >> 5;
    const int wm   = warp & 3;   // 4 warps in M -> 32 rows each
    const int wn   = warp >> 2;  // 2 warps in N -> 64 cols each
    const int gr   = lane >> 2;
    const int tg   = lane & 3;

    // two accumulators per tile (one per ks) -> shorter fp16 accumulation chains
    uint32_t acc[2][2][8][2];
    #pragma unroll
    for (int ks = 0; ks < 2; ks++)
        #pragma unroll
        for (int mt = 0; mt < 2; mt++)
            #pragma unroll
            for (int nt = 0; nt < 8; nt++) {
                acc[ks][mt][nt][0] = 0u;
                acc[ks][mt][nt][1] = 0u;
            }

    const int nk = D / BK;   // 64
    uint4 ar[2], br[2];

    auto gload = [&](int kt) {
        #pragma unroll
        for (int j = 0; j < 2; j++) {
            int i  = tid + TPB * j;     // 0..511
            int r  = i >> 2;            // row 0..127
            int ch = i & 3;             // 8-half chunk within 32-col k-tile
            ar[j] = *(const uint4*)(g_Fh + (size_t)(bm + r) * D + kt * BK + ch * 8);
            br[j] = *(const uint4*)(g_Ch + (size_t)(bn + r) * D + kt * BK + ch * 8);
        }
    };
    auto sstore = [&](int buf) {
        #pragma unroll
        for (int j = 0; j < 2; j++) {
            int i  = tid + TPB * j;
            int r  = i >> 2;
            int ch = i & 3;
            *(uint4*)&As[buf][r * STRIDE + ch * 4] = ar[j];
            *(uint4*)&Bs[buf][r * STRIDE + ch * 4] = br[j];
        }
    };

    gload(0);
    sstore(0);
    __syncthreads();

    // ldmatrix lane-address components (constant across k-tiles):
    // A x4 (per mt, ks): mats = {m0-7@k0, m8-15@k0, m0-7@k8, m8-15@k8} -> a[mt][0..3]
    const int a_mrow = ((lane >> 3) & 1) * 8 + (lane & 7);   // row within 16-row tile
    const int a_koff = ((lane >> 4) & 1) * 4;                // u32 offset within ks half
    // B x4 (per nt-pair p, ks): mats = {n(2p)@k0, n(2p)@k8, n(2p+1)@k0, n(2p+1)@k8}
    const int b_nrow = ((lane >> 4) & 1) * 8 + (lane & 7);   // row within 16-row (2 nt) group
    const int b_koff = ((lane >> 3) & 1) * 4;

    for (int kt = 0; kt < nk; kt++) {
        const int buf = kt & 1;
        if (kt + 1 < nk) gload(kt + 1);

        const uint32_t Abase = smem_u32(&As[buf][0]) + (uint32_t)(((wm * 32 + a_mrow) * STRIDE + a_koff) * 4);
        const uint32_t Bbase = smem_u32(&Bs[buf][0]) + (uint32_t)(((wn * 64 + b_nrow) * STRIDE + b_koff) * 4);

        #pragma unroll
        for (int ks = 0; ks < 2; ks++) {
            const uint32_t koff = (uint32_t)(ks * 8 * 4);
            uint32_t a[2][4];
            #pragma unroll
            for (int mt = 0; mt < 2; mt++)
                ldsm_x4(a[mt], Abase + koff + (uint32_t)(mt * 16 * STRIDE * 4));
            uint32_t bb[8][2];
            #pragma unroll
            for (int p = 0; p < 4; p++) {
                uint32_t r4[4];
                ldsm_x4(r4, Bbase + koff + (uint32_t)(p * 16 * STRIDE * 4));
                bb[2*p][0] = r4[0]; bb[2*p][1] = r4[1];
                bb[2*p+1][0] = r4[2]; bb[2*p+1][1] = r4[3];
            }
            #pragma unroll
            for (int mt = 0; mt < 2; mt++)
                #pragma unroll
                for (int nt = 0; nt < 8; nt++)
                    mma_f16acc(acc[ks][mt][nt], a[mt], bb[nt]);
        }

        if (kt + 1 < nk) {
            sstore(buf ^ 1);   // write other buffer: no hazard with current readers
            __syncthreads();   // single barrier per k-tile
        }
    }

    // epilogue: s = c2[c] - 2*(cross_ks0 + cross_ks1), fp16 pairs -> fp32
    #pragma unroll
    for (int mt = 0; mt < 2; mt++) {
        #pragma unroll
        for (int nt = 0; nt < 8; nt++) {
            float2 l0 = __half22float2(*reinterpret_cast<__half2*>(&acc[0][mt][nt][0]));
            float2 h0 = __half22float2(*reinterpret_cast<__half2*>(&acc[0][mt][nt][1]));
            float2 l1 = __half22float2(*reinterpret_cast<__half2*>(&acc[1][mt][nt][0]));
            float2 h1 = __half22float2(*reinterpret_cast<__half2*>(&acc[1][mt][nt][1]));
            int r0 = bm + wm * 32 + mt * 16 + gr;
            int c0 = bn + wn * 64 + nt * 8 + 2 * tg;
            if (c0 < C) {
                float cc = g_c2[c0];
                g_d2[(size_t)r0 * C + c0]       = cc - 2.0f * (l0.x + l1.x);
                g_d2[(size_t)(r0 + 8) * C + c0] = cc - 2.0f * (h0.x + h1.x);
            }
            if (c0 + 1 < C) {
                float cc = g_c2[c0 + 1];
                g_d2[(size_t)r0 * C + c0 + 1]       = cc - 2.0f * (l0.y + l1.y);
                g_d2[(size_t)(r0 + 8) * C + c0 + 1] = cc - 2.0f * (h0.y + h1.y);
            }
        }
    }
}

// ---------------- min + exact fp32 refinement + threshold mask ----------------
#define MARGIN 8.0f    // ~5 sigma of fp16 accumulation + input-quantization noise in d2

__global__ void __launch_bounds__(TPB) minmask_kernel(
    const float* __restrict__ F, const float* __restrict__ Cn,
    const float* __restrict__ GS, float* __restrict__ mask, int C, int D)
{
    __shared__ float sfeat[2048];
    __shared__ float red[8];
    __shared__ int   s_cand[64];
    __shared__ int   s_ncand;

    const int b   = blockIdx.x;
    const int tid = threadIdx.x;

    float f2p = 0.0f;
    if ((D & 3) == 0) {
        const float4* F4 = (const float4*)(F + (size_t)b * D);
        for (int i = tid; i < (D >> 2); i += TPB) {
            float4 v = F4[i];
            int k = i * 4;
            sfeat[k] = v.x; sfeat[k+1] = v.y; sfeat[k+2] = v.z; sfeat[k+3] = v.w;
            f2p += v.x*v.x + v.y*v.y + v.z*v.z + v.w*v.w;
        }
    } else {
        for (int i = tid; i < D; i += TPB) {
            float v = F[(size_t)b * D + i];
            sfeat[i] = v;
            f2p += v * v;
        }
    }
    float f2 = blockReduceSum(f2p, red);

    const float* srow = g_d2 + (size_t)b * C;
    float mn = 3.4e38f;
    for (int i = tid; i < C; i += TPB) mn = fminf(mn, srow[i]);
    mn = blockReduceMin(mn, red);

    if (tid == 0) s_ncand = 0;
    __syncthreads();
    for (int i = tid; i < C; i += TPB) {
        if (srow[i] <= mn + MARGIN) {
            int j = atomicAdd(&s_ncand, 1);
            if (j < 64) s_cand[j] = i;
        }
    }
    __syncthreads();
    int nc = min(s_ncand, 64);

    // exact fp32 recompute of candidate distances (kills fp16 noise at the decision)
    float best = 3.4e38f;
    for (int j = 0; j < nc; j++) {
        int c = s_cand[j];
        const float* crow = Cn + (size_t)c * D;
        float dp = 0.0f;
        for (int i = tid; i < D; i += TPB) dp += sfeat[i] * crow[i];
        float dot = blockReduceSum(dp, red);
        best = fminf(best, g_c2[c] - 2.0f * dot);
    }

    if (tid == 0) {
        float d2   = f2 + best;
        float dist = sqrtf(fmaxf(d2, 0.0f));
        float T    = GS[0] + 1.5f * GS[1];
        mask[b] = (dist / (T + 1e-8f) > 1.0f) ? 1.0f : 0.0f;
    }
}

__global__ void fill_kernel(float* p, int n)
{
    int i = blockIdx.x * blockDim.x + threadIdx.x;
    if (i < n) p[i] = 0.0f;
}

// ---------------- launch ----------------
extern "C" void kernel_launch(void* const* d_in, const int* in_sizes, int n_in,
                              void* d_out, int out_size)
{
    const float* F  = (const float*)d_in[0];  // features  [B, D]
    const float* P  = (const float*)d_in[1];  // predictions [B, C]
    const float* Cn = (const float*)d_in[2];  // centers [C, D]
    const float* GS = (const float*)d_in[3];  // global_stats [2]

    const int B = in_sizes[4];            // known_labels length
    const int D = in_sizes[0] / B;
    const int C = in_sizes[1] / B;

    float* out   = (float*)d_out;
    float* mask  = out;                   // mask_novel first (return order)
    float* probs = out + B;               // probs second

    softmax_kernel<<<B, TPB>>>(P, probs, C);
    c2_kernel<<<C, TPB>>>(Cn, D);

    int nF8 = (B * D) >> 3;
    int nC8 = (1024 * D) >> 3;
    cvt_kernel<<<(nF8 + nC8 + TPB - 1) / TPB, TPB>>>(F, Cn, nF8, C, D);

    dim3 g((C + BN - 1) / BN, B / BM);    // B=16384 divisible by 128; D=2048 by 32
    gemm_mindist_kernel<<<g, TPB>>>(C, D);

    minmask_kernel<<<B, TPB>>>(F, Cn, GS, mask, C, D);

    long total = (long)B * C + B;
    if ((long)out_size > total) {
        long rem = (long)out_size - total;
        fill_kernel<<<(int)((rem + 255) / 256), 256>>>(out + total, (int)rem);
    }
}